// round 5
// baseline (speedup 1.0000x reference)
#include <cuda_runtime.h>

// ============================================================================
// LocalBranch fused kernel, round 2: fp32 SIMT with packed fma.rn.f32x2
// (Blackwell FFMA2 path, 2x fp32 FMA throughput vs 3-reg FFMA).
// Same fully-fused per-graph-CTA structure as round 1.
// ============================================================================

namespace lb {

using u64 = unsigned long long;

constexpr int TPB   = 512;
constexpr int NODES = 128;
constexpr int IND   = 64;
constexpr int HID   = 256;
constexpr int OUTD  = 128;
constexpr int NBLK  = 3;
constexpr int NG    = 1024;
constexpr int KC    = 16;     // k-chunk for weight staging
constexpr int ZSTR  = 132;    // zT row stride (bank-conflict padding)

constexpr int SX_FLOATS   = NODES * HID;    // 32768
constexpr int SAUX_FLOATS = NODES * ZSTR;   // 16896
constexpr int SW_FLOATS   = KC * HID;       // 4096
constexpr int SMEM_FLOATS = SX_FLOATS + SAUX_FLOATS + SW_FLOATS;
constexpr int SMEM_BYTES  = SMEM_FLOATS * 4;  // 215040 B

__device__ __forceinline__ float warpsum(float v) {
#pragma unroll
    for (int o = 16; o; o >>= 1) v += __shfl_xor_sync(0xffffffffu, v, o);
    return v;
}

// ---- packed f32x2 primitives (SASS FFMA2 path; ptxas won't auto-fuse) ----
__device__ __forceinline__ u64 pack2(float lo, float hi) {
    u64 r;
    asm("mov.b64 %0, {%1, %2};" : "=l"(r) : "f"(lo), "f"(hi));
    return r;
}
__device__ __forceinline__ float2 unpack2(u64 v) {
    float2 r;
    asm("mov.b64 {%0, %1}, %2;" : "=f"(r.x), "=f"(r.y) : "l"(v));
    return r;
}
__device__ __forceinline__ void ffma2(u64& d, u64 a, u64 b) {
    asm("fma.rn.f32x2 %0, %1, %2, %0;" : "+l"(d) : "l"(a), "l"(b));
}
__device__ __forceinline__ u64 addf32x2(u64 a, u64 b) {
    u64 r;
    asm("add.rn.f32x2 %0, %1, %2;" : "=l"(r) : "l"(a), "l"(b));
    return r;
}

// Register-blocked GEMM: C[128, NCOLS] = X[128, KDIM] @ W[KDIM, NCOLS].
// Thread (wid, lane): rows r0..r0+7, packed col pairs starting at c0 = lane*4
// (and c0+128 when NCOLS == 256). Accumulators are f32x2 pairs.
template<int KDIM, int NCOLS>
__device__ __forceinline__ void gemm_tile(
    const float* __restrict__ xin, int xstride,
    const float* __restrict__ Wg,
    float* __restrict__ sw,
    u64 (&acc)[8][4],
    int r0, int c0, int tid)
{
    constexpr int NCH = KDIM / KC;
    constexpr int V4  = (KC * NCOLS) / (TPB * 4);   // float4s per thread
    constexpr int NP  = (NCOLS == 256) ? 4 : 2;     // packed pairs per row

    float4 pre[V4];
    {
        const float4* src = reinterpret_cast<const float4*>(Wg);
#pragma unroll
        for (int q = 0; q < V4; ++q) pre[q] = src[tid * V4 + q];
    }
#pragma unroll
    for (int m = 0; m < 8; ++m)
#pragma unroll
        for (int p = 0; p < NP; ++p) acc[m][p] = 0ull;

#pragma unroll 1
    for (int ch = 0; ch < NCH; ++ch) {
        __syncthreads();   // previous consumers of sw (and sx/saux writers) done
        float4* dst = reinterpret_cast<float4*>(sw);
#pragma unroll
        for (int q = 0; q < V4; ++q) dst[tid * V4 + q] = pre[q];
        __syncthreads();
        if (ch + 1 < NCH) {
            const float4* src =
                reinterpret_cast<const float4*>(Wg + (size_t)(ch + 1) * KC * NCOLS);
#pragma unroll
            for (int q = 0; q < V4; ++q) pre[q] = src[tid * V4 + q];
        }
        const float* xrow = xin + ch * KC;
#pragma unroll 2
        for (int kk = 0; kk < KC; kk += 2) {
            float2 xv[8];
#pragma unroll
            for (int m = 0; m < 8; ++m)
                xv[m] = *reinterpret_cast<const float2*>(
                    &xrow[(r0 + m) * xstride + kk]);
#pragma unroll
            for (int t = 0; t < 2; ++t) {
                ulonglong2 wA = *reinterpret_cast<const ulonglong2*>(
                    &sw[(kk + t) * NCOLS + c0]);
                ulonglong2 wB;
                if constexpr (NCOLS == 256)
                    wB = *reinterpret_cast<const ulonglong2*>(
                        &sw[(kk + t) * NCOLS + c0 + 128]);
#pragma unroll
                for (int m = 0; m < 8; ++m) {
                    float xs = t ? xv[m].y : xv[m].x;
                    u64 xp = pack2(xs, xs);
                    ffma2(acc[m][0], xp, wA.x);
                    ffma2(acc[m][1], xp, wA.y);
                    if constexpr (NCOLS == 256) {
                        ffma2(acc[m][2], xp, wB.x);
                        ffma2(acc[m][3], xp, wB.y);
                    }
                }
            }
        }
    }
}

// LN(+bias) -> relu -> (optional residual) -> write back into sx.
template<bool RES>
__device__ __forceinline__ void epi256(
    u64 (&acc)[8][4], float* __restrict__ sx,
    const float* __restrict__ bias, const float* __restrict__ gamma,
    const float* __restrict__ beta, int r0, int c0)
{
    ulonglong2 bA = *reinterpret_cast<const ulonglong2*>(&bias[c0]);
    ulonglong2 bB = *reinterpret_cast<const ulonglong2*>(&bias[c0 + 128]);
    u64 bp[4] = {bA.x, bA.y, bB.x, bB.y};
    float4 gA = *reinterpret_cast<const float4*>(&gamma[c0]);
    float4 gB = *reinterpret_cast<const float4*>(&gamma[c0 + 128]);
    float4 eA = *reinterpret_cast<const float4*>(&beta[c0]);
    float4 eB = *reinterpret_cast<const float4*>(&beta[c0 + 128]);
    float gv[8] = {gA.x, gA.y, gA.z, gA.w, gB.x, gB.y, gB.z, gB.w};
    float ev[8] = {eA.x, eA.y, eA.z, eA.w, eB.x, eB.y, eB.z, eB.w};
    float mu[8], rs[8];
#pragma unroll
    for (int m = 0; m < 8; ++m) {
        float s1 = 0.f, s2 = 0.f;
#pragma unroll
        for (int p = 0; p < 4; ++p) {
            acc[m][p] = addf32x2(acc[m][p], bp[p]);   // biased value kept packed
            float2 q = unpack2(acc[m][p]);
            s1 += q.x + q.y;
            s2 = fmaf(q.x, q.x, s2);
            s2 = fmaf(q.y, q.y, s2);
        }
        s1 = warpsum(s1);
        s2 = warpsum(s2);
        float m_ = s1 * (1.f / 256.f);
        mu[m] = m_;
        rs[m] = rsqrtf(fmaf(-m_, m_, s2 * (1.f / 256.f)) + 1e-5f);
    }
    __syncthreads();   // all GEMM reads of sx complete before we overwrite
#pragma unroll
    for (int m = 0; m < 8; ++m) {
        float o[8];
#pragma unroll
        for (int p = 0; p < 4; ++p) {
            float2 q = unpack2(acc[m][p]);
            float v0 = fmaf((q.x - mu[m]) * rs[m], gv[2 * p], ev[2 * p]);
            float v1 = fmaf((q.y - mu[m]) * rs[m], gv[2 * p + 1], ev[2 * p + 1]);
            o[2 * p]     = fmaxf(v0, 0.f);
            o[2 * p + 1] = fmaxf(v1, 0.f);
        }
        float* row = &sx[(r0 + m) * HID];
        if (RES) {
            float4 oA = *reinterpret_cast<const float4*>(&row[c0]);
            float4 oB = *reinterpret_cast<const float4*>(&row[c0 + 128]);
            o[0] += oA.x; o[1] += oA.y; o[2] += oA.z; o[3] += oA.w;
            o[4] += oB.x; o[5] += oB.y; o[6] += oB.z; o[7] += oB.w;
        }
        *reinterpret_cast<float4*>(&row[c0]) = make_float4(o[0], o[1], o[2], o[3]);
        *reinterpret_cast<float4*>(&row[c0 + 128]) =
            make_float4(o[4], o[5], o[6], o[7]);
    }
}

__global__ void __launch_bounds__(TPB, 1)
fused_local_branch(const float* __restrict__ H,
                   const float* __restrict__ W_in, const float* __restrict__ b_in,
                   const float* __restrict__ g_in, const float* __restrict__ be_in,
                   const float* __restrict__ Wb, const float* __restrict__ bbias,
                   const float* __restrict__ gb, const float* __restrict__ betab,
                   const float* __restrict__ W_out, const float* __restrict__ b_out,
                   const float* __restrict__ g_out, const float* __restrict__ be_out,
                   float* __restrict__ out)
{
    extern __shared__ float sm[];
    float* sx   = sm;                          // [128][256]
    float* saux = sm + SX_FLOATS;              // H tile, then zT [128][132]
    float* sw   = sm + SX_FLOATS + SAUX_FLOATS;// weight stage / scratch

    const int tid  = threadIdx.x;
    const int lane = tid & 31;
    const int wid  = tid >> 5;
    const int r0   = wid * 8;
    const int c0   = lane * 4;
    const int g    = blockIdx.x;

    // --- load H tile [128,64] into saux ---
    {
        const float4* src =
            reinterpret_cast<const float4*>(H + (size_t)g * NODES * IND);
        float4* dst = reinterpret_cast<float4*>(saux);
#pragma unroll
        for (int q = 0; q < (NODES * IND / 4) / TPB; ++q)
            dst[tid + q * TPB] = src[tid + q * TPB];
    }
    // (gemm_tile's leading __syncthreads orders these STS before use)

    u64 acc[8][4];

    // --- stem: x = relu(LN(H @ W_in + b_in)) ---
    gemm_tile<IND, HID>(saux, IND, W_in, sw, acc, r0, c0, tid);
    epi256<false>(acc, sx, b_in, g_in, be_in, r0, c0);

    // --- residual blocks ---
    for (int blk = 0; blk < NBLK; ++blk) {
        gemm_tile<HID, HID>(sx, HID, Wb + (size_t)blk * HID * HID, sw, acc,
                            r0, c0, tid);
        epi256<true>(acc, sx, bbias + blk * HID, gb + blk * HID,
                     betab + blk * HID, r0, c0);
    }

    // --- head: z = LN(x @ W_out + b_out), stored transposed zT[dim][node] ---
    gemm_tile<HID, OUTD>(sx, HID, W_out, sw, acc, r0, c0, tid);
    {
        ulonglong2 b2 = *reinterpret_cast<const ulonglong2*>(&b_out[c0]);
        u64 bp[2] = {b2.x, b2.y};
        float4 g4 = *reinterpret_cast<const float4*>(&g_out[c0]);
        float4 e4 = *reinterpret_cast<const float4*>(&be_out[c0]);
        float gv[4] = {g4.x, g4.y, g4.z, g4.w};
        float ev[4] = {e4.x, e4.y, e4.z, e4.w};
#pragma unroll
        for (int m = 0; m < 8; ++m) {
            float s1 = 0.f, s2 = 0.f;
            float v[4];
#pragma unroll
            for (int p = 0; p < 2; ++p) {
                acc[m][p] = addf32x2(acc[m][p], bp[p]);
                float2 q = unpack2(acc[m][p]);
                v[2 * p] = q.x; v[2 * p + 1] = q.y;
                s1 += q.x + q.y;
                s2 = fmaf(q.x, q.x, s2);
                s2 = fmaf(q.y, q.y, s2);
            }
            s1 = warpsum(s1);
            s2 = warpsum(s2);
            float mu = s1 * (1.f / 128.f);
            float rs = rsqrtf(fmaf(-mu, mu, s2 * (1.f / 128.f)) + 1e-5f);
#pragma unroll
            for (int n = 0; n < 4; ++n) {
                float z = fmaf((v[n] - mu) * rs, gv[n], ev[n]);
                saux[(c0 + n) * ZSTR + (r0 + m)] = z;   // zT[dim][node]
            }
        }
    }
    __syncthreads();

    // --- squared norms sq[i], zero s accumulator ---
    if (tid < NODES) {
        float s = 0.f;
#pragma unroll 4
        for (int d = 0; d < OUTD; ++d) {
            float v = saux[d * ZSTR + tid];
            s = fmaf(v, v, s);
        }
        sw[tid] = s;                                    // sq
    } else if (tid >= TPB - NODES) {
        sw[NODES + (tid - (TPB - NODES))] = 0.f;        // s sums
    }
    __syncthreads();

    // --- pairwise: thread covers i = c0..c0+3 (lanes), j = r0..r0+7 (warps) ---
    {
        u64 dot2[8][2];
#pragma unroll
        for (int j = 0; j < 8; ++j) { dot2[j][0] = 0ull; dot2[j][1] = 0ull; }

#pragma unroll 2
        for (int d = 0; d < OUTD; ++d) {
            ulonglong2 zi = *reinterpret_cast<const ulonglong2*>(
                &saux[d * ZSTR + c0]);
#pragma unroll
            for (int j = 0; j < 8; ++j) {
                float zj = saux[d * ZSTR + r0 + j];     // broadcast
                u64 zp = pack2(zj, zj);
                ffma2(dot2[j][0], zp, zi.x);
                ffma2(dot2[j][1], zp, zi.y);
            }
        }
        float sqi[4];
#pragma unroll
        for (int n = 0; n < 4; ++n) sqi[n] = sw[c0 + n];
        float sacc[4] = {0.f, 0.f, 0.f, 0.f};
#pragma unroll
        for (int j = 0; j < 8; ++j) {
            float sqj = sw[r0 + j];
            float2 q0 = unpack2(dot2[j][0]);
            float2 q1 = unpack2(dot2[j][1]);
            float dv[4] = {q0.x, q0.y, q1.x, q1.y};
#pragma unroll
            for (int n = 0; n < 4; ++n) {
                float d2 = sqi[n] + sqj - 2.f * dv[n];
                sacc[n] += sqrtf(fmaxf(d2, 0.f) + 1e-12f);
            }
        }
#pragma unroll
        for (int n = 0; n < 4; ++n)
            atomicAdd(&sw[NODES + c0 + n], sacc[n]);
    }
    __syncthreads();

    // --- softmax over 128 logits (warp 0): logits = (ssum/128)/TAU ---
    if (wid == 0) {
        const float scale = 1.f / (128.f * 0.25f);
        float sv[4], mx = -1e30f;
#pragma unroll
        for (int q = 0; q < 4; ++q) {
            sv[q] = sw[NODES + lane + 32 * q] * scale;
            mx = fmaxf(mx, sv[q]);
        }
#pragma unroll
        for (int o = 16; o; o >>= 1)
            mx = fmaxf(mx, __shfl_xor_sync(0xffffffffu, mx, o));
        float e[4], se = 0.f;
#pragma unroll
        for (int q = 0; q < 4; ++q) {
            e[q] = expf(sv[q] - mx);
            se += e[q];
        }
        se = warpsum(se);
        float inv = 1.f / se;
#pragma unroll
        for (int q = 0; q < 4; ++q) {
            float w_ = e[q] * inv;
            int i = lane + 32 * q;
            sw[2 * NODES + i] = w_;
            out[(size_t)NG * OUTD + (size_t)g * NODES + i] = w_;
        }
    }
    __syncthreads();

    // --- v[d] = sum_i w_i * z[i][d] ---
    if (tid < OUTD) {
        float a = 0.f;
#pragma unroll 4
        for (int i = 0; i < NODES; ++i)
            a = fmaf(sw[2 * NODES + i], saux[tid * ZSTR + i], a);
        out[(size_t)g * OUTD + tid] = a;
    }
}

}  // namespace lb

extern "C" void kernel_launch(void* const* d_in, const int* in_sizes, int n_in,
                              void* d_out, int out_size)
{
    (void)in_sizes; (void)n_in; (void)out_size;
    const float* H     = (const float*)d_in[0];
    // d_in[1] = batch_ptr (uniform graphs; unused)
    const float* W_in  = (const float*)d_in[2];
    const float* b_in  = (const float*)d_in[3];
    const float* g_in  = (const float*)d_in[4];
    const float* be_in = (const float*)d_in[5];
    const float* Wb    = (const float*)d_in[6];
    const float* bb    = (const float*)d_in[7];
    const float* gb    = (const float*)d_in[8];
    const float* betab = (const float*)d_in[9];
    const float* W_out = (const float*)d_in[10];
    const float* b_out = (const float*)d_in[11];
    const float* g_out = (const float*)d_in[12];
    const float* be_out= (const float*)d_in[13];
    float* out = (float*)d_out;

    cudaFuncSetAttribute(lb::fused_local_branch,
                         cudaFuncAttributeMaxDynamicSharedMemorySize,
                         lb::SMEM_BYTES);

    lb::fused_local_branch<<<lb::NG, lb::TPB, lb::SMEM_BYTES>>>(
        H, W_in, b_in, g_in, be_in, Wb, bb, gb, betab,
        W_out, b_out, g_out, be_out, out);
}

// round 7
// speedup vs baseline: 2.6407x; 2.6407x over previous
#include <cuda_runtime.h>
#include <cuda_bf16.h>
#include <cstdint>

// ============================================================================
// LocalBranch round 7: bf16x3 (hi/lo split, 3-term) GEMMs on mma.sync
// (m16n8k16, sm_80-class PTX -- harness targets base sm_103, no tcgen05).
//  - per-graph CTA, 512 thr = 16 warps, warp tile 32x64 (or 32x32)
//  - x kept as hi/lo bf16 planes in SMEM (k-major, padded, ldmatrix-friendly)
//  - weights pre-split/transposed into __device__ image; cp.async k32 ring
//  - LN/relu/residual epilogues in fp32 on register accumulators
//  - Gram = Z @ Z^T on the same path, exact diagonal; softmax/pool SIMT
// ============================================================================

namespace lb {

using u32 = uint32_t;

constexpr int TPB = 512, NODES = 128, IND = 64, HID = 256, OUTD = 128,
              NBLK = 3, NG = 1024;

// SMEM layout (bytes)
constexpr int XS_RS = 528;                 // x-plane row stride (264 bf16)
constexpr int XS_PL = 128 * XS_RS;         // 67584 per plane
constexpr int XS_HI = 0;
constexpr int XS_LO = XS_PL;
constexpr int RING  = 2 * XS_PL;           // 135168 (2 weight slots; later zT)
constexpr int SLOT  = 40960;
constexpr int SCR   = RING + 2 * SLOT;     // 217088
constexpr int SC_PART = SCR;               // float2[128*4]
constexpr int SC_SQ   = SCR + 4096;        // float[128]
constexpr int SC_S    = SCR + 4608;        // float[128]
constexpr int SC_W    = SCR + 5120;        // float[128]
constexpr int SMEM_BYTES = SCR + 5632;     // 222720

// Weight image: per GEMM, k32 chunks; chunk = [hi plane][lo plane],
// plane = N rows x 40 bf16 (80 B, padded) in n-major (W^T) order.
constexpr int IMG_STEM = 0;                           // 2 chunks x 40960
constexpr int IMG_BLK  = 81920;                       // 3 x 8 x 40960
constexpr int IMG_BLKSTR = 327680;
constexpr int IMG_HEAD = 1064960;                     // 8 x 20480
__device__ __align__(16) unsigned char g_wimg[1228800];

// ---------------- PTX helpers ----------------
__device__ __forceinline__ u32 s2u(const void* p) {
    u32 a;
    asm("{ .reg .u64 t; cvta.to.shared.u64 t, %1; cvt.u32.u64 %0, t; }"
        : "=r"(a) : "l"(p));
    return a;
}
__device__ __forceinline__ void ldsm4(u32* r, u32 addr) {
    asm volatile("ldmatrix.sync.aligned.m8n8.x4.shared.b16 {%0,%1,%2,%3}, [%4];"
                 : "=r"(r[0]), "=r"(r[1]), "=r"(r[2]), "=r"(r[3]) : "r"(addr));
}
__device__ __forceinline__ void mma16816(float* c, const u32* a, u32 b0, u32 b1) {
    asm volatile(
        "mma.sync.aligned.m16n8k16.row.col.f32.bf16.bf16.f32 "
        "{%0,%1,%2,%3}, {%4,%5,%6,%7}, {%8,%9}, {%0,%1,%2,%3};"
        : "+f"(c[0]), "+f"(c[1]), "+f"(c[2]), "+f"(c[3])
        : "r"(a[0]), "r"(a[1]), "r"(a[2]), "r"(a[3]), "r"(b0), "r"(b1));
}
__device__ __forceinline__ void cpa16(u32 dst, const void* src) {
    asm volatile("cp.async.cg.shared.global [%0], [%1], 16;"
                 :: "r"(dst), "l"(src) : "memory");
}
__device__ __forceinline__ void cp_commit() {
    asm volatile("cp.async.commit_group;" ::: "memory");
}
__device__ __forceinline__ void cp_wait1() {
    asm volatile("cp.async.wait_group 1;" ::: "memory");
}
__device__ __forceinline__ void cp_wait0() {
    asm volatile("cp.async.wait_group 0;" ::: "memory");
}

// ---------------- bf16 pack helpers ----------------
__device__ __forceinline__ u32 packbf(float x0, float x1) {
    unsigned short a = __bfloat16_as_ushort(__float2bfloat16(x0));
    unsigned short b = __bfloat16_as_ushort(__float2bfloat16(x1));
    return (u32)a | ((u32)b << 16);
}
__device__ __forceinline__ float bflo(u32 p) {
    return __bfloat162float(__ushort_as_bfloat16((unsigned short)(p & 0xffff)));
}
__device__ __forceinline__ float bfhi(u32 p) {
    return __bfloat162float(__ushort_as_bfloat16((unsigned short)(p >> 16)));
}

// ---------------- prep: weights -> split/transposed padded image ----------
__global__ void prep(const float* __restrict__ Wi, const float* __restrict__ Wb,
                     const float* __restrict__ Wo) {
    int idx = blockIdx.x * 256 + threadIdx.x;        // 245760 total
    const float* W; int k, n, N; long base; int cstr;
    if (idx < 16384) {
        W = Wi; N = 256; k = idx >> 8; n = idx & 255;
        base = IMG_STEM; cstr = 40960;
    } else if (idx < 212992) {
        int e = idx - 16384; int b = e >> 16; e &= 65535;
        W = Wb + (size_t)b * 65536; N = 256; k = e >> 8; n = e & 255;
        base = IMG_BLK + (long)b * IMG_BLKSTR; cstr = 40960;
    } else {
        int e = idx - 212992;
        W = Wo; N = 128; k = e >> 7; n = e & 127;
        base = IMG_HEAD; cstr = 20480;
    }
    float w = W[(size_t)k * N + n];
    __nv_bfloat16 h = __float2bfloat16(w);
    __nv_bfloat16 l = __float2bfloat16(w - __bfloat162float(h));
    long off = base + (long)(k >> 5) * cstr + (long)n * 80 + (k & 31) * 2;
    *(__nv_bfloat16*)(g_wimg + off) = h;
    *(__nv_bfloat16*)(g_wimg + off + (long)N * 80) = l;
}

// ---------------- staged GEMM: acc += X(planes) @ W(img), 3-term ----------
template<int N>   // 256 or 128
__device__ __forceinline__ void gemm_run(
    u32 smb, unsigned char* smc, const unsigned char* img, int nchunk,
    float (&acc)[2][8][4], int tid, int m0, int nq,
    int a_row, int a_kh, int b_n, int b_kh)
{
    constexpr int NP = N / 64;                 // ldsm-pairs of n8 tiles
    constexpr int CB = N * 160;                // chunk bytes (2 planes)
    constexpr int LINES = CB / 16;
    const int n0 = nq * (N / 4);

    const u32 axh = smb + XS_HI + (u32)(m0 + a_row) * XS_RS + a_kh * 16;
    const u32 axl = axh + XS_PL;
    const u32 wtb = (u32)(n0 + b_n) * 80 + b_kh * 16;

#pragma unroll
    for (int mt = 0; mt < 2; ++mt)
#pragma unroll
        for (int nt = 0; nt < 8; ++nt)
#pragma unroll
            for (int e = 0; e < 4; ++e) acc[mt][nt][e] = 0.f;

    // issue chunk 0
    {
        u32 dst = smb + RING;
        const unsigned char* src = img;
        for (int i = tid; i < LINES; i += TPB) cpa16(dst + i * 16, src + i * 16);
        cp_commit();
    }

    for (int ch = 0; ch < nchunk; ++ch) {
        if (ch + 1 < nchunk) {
            u32 dst = smb + RING + ((ch + 1) & 1) * SLOT;
            const unsigned char* src = img + (size_t)(ch + 1) * CB;
            for (int i = tid; i < LINES; i += TPB) cpa16(dst + i * 16, src + i * 16);
            cp_commit();
            cp_wait1();
        } else {
            cp_wait0();
        }
        __syncthreads();
        const u32 slot = smb + RING + (ch & 1) * SLOT;
#pragma unroll
        for (int ks = 0; ks < 2; ++ks) {
            const u32 kb = (u32)ch * 64 + ks * 32;
            u32 ah0[4], ah1[4], al0[4], al1[4];
            ldsm4(ah0, axh + kb);
            ldsm4(ah1, axh + 16 * XS_RS + kb);
            ldsm4(al0, axl + kb);
            ldsm4(al1, axl + 16 * XS_RS + kb);
#pragma unroll
            for (int np = 0; np < NP; ++np) {
                const u32 wa = slot + wtb + (u32)np * 16 * 80 + ks * 32;
                u32 bh[4], bl[4];
                ldsm4(bh, wa);
                ldsm4(bl, wa + N * 80);
#pragma unroll
                for (int h = 0; h < 2; ++h) {
                    float* c0 = acc[0][np * 2 + h];
                    float* c1 = acc[1][np * 2 + h];
                    mma16816(c0, ah0, bh[2 * h], bh[2 * h + 1]);
                    mma16816(c0, al0, bh[2 * h], bh[2 * h + 1]);
                    mma16816(c0, ah0, bl[2 * h], bl[2 * h + 1]);
                    mma16816(c1, ah1, bh[2 * h], bh[2 * h + 1]);
                    mma16816(c1, al1, bh[2 * h], bh[2 * h + 1]);
                    mma16816(c1, ah1, bl[2 * h], bl[2 * h + 1]);
                }
            }
        }
        __syncthreads();
    }
}

// ---------------- main kernel ----------------
__global__ void __launch_bounds__(TPB, 1)
fused(const float* __restrict__ H,
      const float* __restrict__ b_in, const float* __restrict__ g_in,
      const float* __restrict__ be_in,
      const float* __restrict__ bb, const float* __restrict__ gb,
      const float* __restrict__ betab,
      const float* __restrict__ b_out, const float* __restrict__ g_out,
      const float* __restrict__ be_out,
      float* __restrict__ out)
{
    extern __shared__ __align__(16) unsigned char smc[];
    const u32 smb = s2u(smc);
    const int tid = threadIdx.x, lane = tid & 31, w = tid >> 5;
    const int qr = lane >> 2, qc = lane & 3;
    const int mq = w & 3, nq = w >> 2;
    const int m0 = mq * 32;
    const int grp = lane >> 3, ri = lane & 7;
    const int a_row = (grp & 1) * 8 + ri, a_kh = grp >> 1;
    const int b_n = (grp >> 1) * 8 + ri,  b_kh = grp & 1;
    const int g = blockIdx.x;

    float2* part = (float2*)(smc + SC_PART);
    float* sqv = (float*)(smc + SC_SQ);
    float* ssm = (float*)(smc + SC_S);
    float* wsm = (float*)(smc + SC_W);

    // ---- stem A: H -> hi/lo bf16 planes (k = 0..63) ----
    {
        const int row = tid >> 2, c4 = tid & 3;
        const float4* hs = (const float4*)(H + (size_t)g * NODES * IND
                                           + (size_t)row * IND + c4 * 16);
        const u32 off = (u32)row * XS_RS + (u32)c4 * 32;
#pragma unroll
        for (int q = 0; q < 4; ++q) {
            float4 v = hs[q];
            u32 h0 = packbf(v.x, v.y), h1 = packbf(v.z, v.w);
            u32 l0 = packbf(v.x - bflo(h0), v.y - bfhi(h0));
            u32 l1 = packbf(v.z - bflo(h1), v.w - bfhi(h1));
            *(u32*)(smc + XS_HI + off + q * 8)     = h0;
            *(u32*)(smc + XS_HI + off + q * 8 + 4) = h1;
            *(u32*)(smc + XS_LO + off + q * 8)     = l0;
            *(u32*)(smc + XS_LO + off + q * 8 + 4) = l1;
        }
    }
    // (gemm_run's post-copy __syncthreads orders these STS before ldmatrix)

    float acc[2][8][4];

    // ---- LN(+relu,+residual) epilogue for N=256, rewrites x planes ----
    auto ep256 = [&](const float* bias, const float* gam, const float* bet,
                     bool res) {
        const int n0 = nq * 64;
        float s1[4] = {0.f, 0.f, 0.f, 0.f}, s2[4] = {0.f, 0.f, 0.f, 0.f};
#pragma unroll
        for (int nt = 0; nt < 8; ++nt) {
            float2 bp = *(const float2*)&bias[n0 + nt * 8 + qc * 2];
#pragma unroll
            for (int mt = 0; mt < 2; ++mt) {
                float* c = acc[mt][nt];
                c[0] += bp.x; c[1] += bp.y; c[2] += bp.x; c[3] += bp.y;
                s1[mt*2]   += c[0] + c[1];
                s2[mt*2]    = fmaf(c[0], c[0], fmaf(c[1], c[1], s2[mt*2]));
                s1[mt*2+1] += c[2] + c[3];
                s2[mt*2+1]  = fmaf(c[2], c[2], fmaf(c[3], c[3], s2[mt*2+1]));
            }
        }
#pragma unroll
        for (int r = 0; r < 4; ++r) {
            s1[r] += __shfl_xor_sync(0xffffffffu, s1[r], 1);
            s1[r] += __shfl_xor_sync(0xffffffffu, s1[r], 2);
            s2[r] += __shfl_xor_sync(0xffffffffu, s2[r], 1);
            s2[r] += __shfl_xor_sync(0xffffffffu, s2[r], 2);
        }
        if (qc == 0) {
#pragma unroll
            for (int r = 0; r < 4; ++r) {
                int row = m0 + (r >> 1) * 16 + (r & 1) * 8 + qr;
                part[row * 4 + nq] = make_float2(s1[r], s2[r]);
            }
        }
        __syncthreads();
        float mu[4], rs[4];
#pragma unroll
        for (int r = 0; r < 4; ++r) {
            int row = m0 + (r >> 1) * 16 + (r & 1) * 8 + qr;
            float4 p0 = *(float4*)&part[row * 4];
            float4 p1 = *(float4*)&part[row * 4 + 2];
            float S1 = p0.x + p0.z + p1.x + p1.z;
            float S2 = p0.y + p0.w + p1.y + p1.w;
            float m_ = S1 * (1.f / 256.f);
            mu[r] = m_;
            rs[r] = rsqrtf(fmaf(-m_, m_, S2 * (1.f / 256.f)) + 1e-5f);
        }
        __syncthreads();
#pragma unroll
        for (int nt = 0; nt < 8; ++nt) {
            int col = n0 + nt * 8 + qc * 2;
            float2 gg = *(const float2*)&gam[col];
            float2 ee = *(const float2*)&bet[col];
#pragma unroll
            for (int mt = 0; mt < 2; ++mt)
#pragma unroll
                for (int h = 0; h < 2; ++h) {
                    int r4 = mt * 2 + h;
                    int row = m0 + mt * 16 + h * 8 + qr;
                    float v0 = acc[mt][nt][2 * h], v1 = acc[mt][nt][2 * h + 1];
                    float y0 = fmaxf(fmaf((v0 - mu[r4]) * rs[r4], gg.x, ee.x), 0.f);
                    float y1 = fmaxf(fmaf((v1 - mu[r4]) * rs[r4], gg.y, ee.y), 0.f);
                    u32 off = (u32)row * XS_RS + (u32)col * 2;
                    if (res) {
                        u32 oh = *(u32*)(smc + XS_HI + off);
                        u32 ol = *(u32*)(smc + XS_LO + off);
                        y0 += bflo(oh) + bflo(ol);
                        y1 += bfhi(oh) + bfhi(ol);
                    }
                    u32 hh = packbf(y0, y1);
                    u32 ll = packbf(y0 - bflo(hh), y1 - bfhi(hh));
                    *(u32*)(smc + XS_HI + off) = hh;
                    *(u32*)(smc + XS_LO + off) = ll;
                }
        }
        __syncthreads();
    };

    // ---- pipeline: stem + 3 residual blocks ----
    gemm_run<256>(smb, smc, g_wimg + IMG_STEM, 2, acc, tid, m0, nq,
                  a_row, a_kh, b_n, b_kh);
    ep256(b_in, g_in, be_in, false);
    for (int b = 0; b < NBLK; ++b) {
        gemm_run<256>(smb, smc, g_wimg + IMG_BLK + (size_t)b * IMG_BLKSTR, 8,
                      acc, tid, m0, nq, a_row, a_kh, b_n, b_kh);
        ep256(bb + b * HID, gb + b * HID, betab + b * HID, true);
    }

    // ---- head GEMM + epilogue: z = LN(x@W_out+b_out) ----
    gemm_run<128>(smb, smc, g_wimg + IMG_HEAD, 8, acc, tid, m0, nq,
                  a_row, a_kh, b_n, b_kh);
    {
        const int n0 = nq * 32;
        float s1[4] = {0.f, 0.f, 0.f, 0.f}, s2[4] = {0.f, 0.f, 0.f, 0.f};
#pragma unroll
        for (int nt = 0; nt < 4; ++nt) {
            float2 bp = *(const float2*)&b_out[n0 + nt * 8 + qc * 2];
#pragma unroll
            for (int mt = 0; mt < 2; ++mt) {
                float* c = acc[mt][nt];
                c[0] += bp.x; c[1] += bp.y; c[2] += bp.x; c[3] += bp.y;
                s1[mt*2]   += c[0] + c[1];
                s2[mt*2]    = fmaf(c[0], c[0], fmaf(c[1], c[1], s2[mt*2]));
                s1[mt*2+1] += c[2] + c[3];
                s2[mt*2+1]  = fmaf(c[2], c[2], fmaf(c[3], c[3], s2[mt*2+1]));
            }
        }
#pragma unroll
        for (int r = 0; r < 4; ++r) {
            s1[r] += __shfl_xor_sync(0xffffffffu, s1[r], 1);
            s1[r] += __shfl_xor_sync(0xffffffffu, s1[r], 2);
            s2[r] += __shfl_xor_sync(0xffffffffu, s2[r], 1);
            s2[r] += __shfl_xor_sync(0xffffffffu, s2[r], 2);
        }
        if (qc == 0) {
#pragma unroll
            for (int r = 0; r < 4; ++r) {
                int row = m0 + (r >> 1) * 16 + (r & 1) * 8 + qr;
                part[row * 4 + nq] = make_float2(s1[r], s2[r]);
            }
        }
        __syncthreads();
        float mu[4], rs[4];
#pragma unroll
        for (int r = 0; r < 4; ++r) {
            int row = m0 + (r >> 1) * 16 + (r & 1) * 8 + qr;
            float4 p0 = *(float4*)&part[row * 4];
            float4 p1 = *(float4*)&part[row * 4 + 2];
            float S1 = p0.x + p0.z + p1.x + p1.z;
            float S2 = p0.y + p0.w + p1.y + p1.w;
            float m_ = S1 * (1.f / 128.f);
            mu[r] = m_;
            rs[r] = rsqrtf(fmaf(-m_, m_, S2 * (1.f / 128.f)) + 1e-5f);
        }
        __syncthreads();
        float* ztf = (float*)(smc + RING);     // zT[dim][132] fp32 (ring free)
        float sqp[4] = {0.f, 0.f, 0.f, 0.f};
#pragma unroll
        for (int nt = 0; nt < 4; ++nt) {
            int col = n0 + nt * 8 + qc * 2;
            float2 gg = *(const float2*)&g_out[col];
            float2 ee = *(const float2*)&be_out[col];
#pragma unroll
            for (int mt = 0; mt < 2; ++mt)
#pragma unroll
                for (int h = 0; h < 2; ++h) {
                    int r4 = mt * 2 + h;
                    int row = m0 + mt * 16 + h * 8 + qr;
                    float z0 = fmaf((acc[mt][nt][2*h]   - mu[r4]) * rs[r4], gg.x, ee.x);
                    float z1 = fmaf((acc[mt][nt][2*h+1] - mu[r4]) * rs[r4], gg.y, ee.y);
                    u32 off = (u32)row * XS_RS + (u32)col * 2;
                    u32 hh = packbf(z0, z1);
                    u32 ll = packbf(z0 - bflo(hh), z1 - bfhi(hh));
                    *(u32*)(smc + XS_HI + off) = hh;   // z planes overlay x
                    *(u32*)(smc + XS_LO + off) = ll;
                    ztf[col * 132 + row] = z0;
                    ztf[(col + 1) * 132 + row] = z1;
                    sqp[r4] = fmaf(z0, z0, fmaf(z1, z1, sqp[r4]));
                }
        }
#pragma unroll
        for (int r = 0; r < 4; ++r) {
            sqp[r] += __shfl_xor_sync(0xffffffffu, sqp[r], 1);
            sqp[r] += __shfl_xor_sync(0xffffffffu, sqp[r], 2);
        }
        if (qc == 0) {
#pragma unroll
            for (int r = 0; r < 4; ++r) {
                int row = m0 + (r >> 1) * 16 + (r & 1) * 8 + qr;
                part[row * 4 + nq].x = sqp[r];
            }
        }
        __syncthreads();
        if (nq == 0 && qc == 0) {
#pragma unroll
            for (int r = 0; r < 4; ++r) {
                int row = m0 + (r >> 1) * 16 + (r & 1) * 8 + qr;
                sqv[row] = part[row*4].x + part[row*4+1].x
                         + part[row*4+2].x + part[row*4+3].x;
            }
        }
        __syncthreads();
    }

    // ---- Gram: dot(i,j) = z_i . z_j via bf16x3 mma from z planes ----
    {
#pragma unroll
        for (int mt = 0; mt < 2; ++mt)
#pragma unroll
            for (int nt = 0; nt < 4; ++nt)
#pragma unroll
                for (int e = 0; e < 4; ++e) acc[mt][nt][e] = 0.f;
        const int n0 = nq * 32;
        const u32 azh = smb + XS_HI + (u32)(m0 + a_row) * XS_RS + a_kh * 16;
        const u32 azl = azh + XS_PL;
        const u32 bzh = smb + XS_HI + (u32)(n0 + b_n) * XS_RS + b_kh * 16;
        const u32 bzl = bzh + XS_PL;
#pragma unroll
        for (int ks = 0; ks < 8; ++ks) {
            const u32 kb = (u32)ks * 32;
            u32 ah0[4], ah1[4], al0[4], al1[4];
            ldsm4(ah0, azh + kb);
            ldsm4(ah1, azh + 16 * XS_RS + kb);
            ldsm4(al0, azl + kb);
            ldsm4(al1, azl + 16 * XS_RS + kb);
#pragma unroll
            for (int np = 0; np < 2; ++np) {
                u32 bh[4], bl[4];
                ldsm4(bh, bzh + (u32)np * 16 * XS_RS + kb);
                ldsm4(bl, bzl + (u32)np * 16 * XS_RS + kb);
#pragma unroll
                for (int h = 0; h < 2; ++h) {
                    float* c0 = acc[0][np * 2 + h];
                    float* c1 = acc[1][np * 2 + h];
                    mma16816(c0, ah0, bh[2*h], bh[2*h+1]);
                    mma16816(c0, al0, bh[2*h], bh[2*h+1]);
                    mma16816(c0, ah0, bl[2*h], bl[2*h+1]);
                    mma16816(c1, ah1, bh[2*h], bh[2*h+1]);
                    mma16816(c1, al1, bh[2*h], bh[2*h+1]);
                    mma16816(c1, ah1, bl[2*h], bl[2*h+1]);
                }
            }
        }
        // distances -> per-row sums
        float sa[4] = {0.f, 0.f, 0.f, 0.f};
#pragma unroll
        for (int nt = 0; nt < 4; ++nt) {
            int col = n0 + nt * 8 + qc * 2;
            float sc0 = sqv[col], sc1 = sqv[col + 1];
#pragma unroll
            for (int mt = 0; mt < 2; ++mt)
#pragma unroll
                for (int h = 0; h < 2; ++h) {
                    int r4 = mt * 2 + h;
                    int row = m0 + mt * 16 + h * 8 + qr;
                    float sr = sqv[row];
                    float d0 = sr + sc0 - 2.f * acc[mt][nt][2 * h];
                    float d1 = sr + sc1 - 2.f * acc[mt][nt][2 * h + 1];
                    float t0 = (col == row) ? 1e-6f
                               : sqrtf(fmaxf(d0, 0.f) + 1e-12f);
                    float t1 = (col + 1 == row) ? 1e-6f
                               : sqrtf(fmaxf(d1, 0.f) + 1e-12f);
                    sa[r4] += t0 + t1;
                }
        }
#pragma unroll
        for (int r = 0; r < 4; ++r) {
            sa[r] += __shfl_xor_sync(0xffffffffu, sa[r], 1);
            sa[r] += __shfl_xor_sync(0xffffffffu, sa[r], 2);
        }
        if (qc == 0) {
#pragma unroll
            for (int r = 0; r < 4; ++r) {
                int row = m0 + (r >> 1) * 16 + (r & 1) * 8 + qr;
                part[row * 4 + nq].x = sa[r];
            }
        }
        __syncthreads();
        if (nq == 0 && qc == 0) {
#pragma unroll
            for (int r = 0; r < 4; ++r) {
                int row = m0 + (r >> 1) * 16 + (r & 1) * 8 + qr;
                ssm[row] = (part[row*4].x + part[row*4+1].x
                          + part[row*4+2].x + part[row*4+3].x) * (1.f / 128.f);
            }
        }
        __syncthreads();
    }

    // ---- softmax over 128 logits (warp 0) ----
    if (w == 0) {
        const float sc = 1.f / 0.25f;
        float sv[4], mx = -1e30f;
#pragma unroll
        for (int q = 0; q < 4; ++q) {
            sv[q] = ssm[lane + 32 * q] * sc;
            mx = fmaxf(mx, sv[q]);
        }
#pragma unroll
        for (int o = 16; o; o >>= 1)
            mx = fmaxf(mx, __shfl_xor_sync(0xffffffffu, mx, o));
        float e[4], se = 0.f;
#pragma unroll
        for (int q = 0; q < 4; ++q) { e[q] = expf(sv[q] - mx); se += e[q]; }
#pragma unroll
        for (int o = 16; o; o >>= 1) se += __shfl_xor_sync(0xffffffffu, se, o);
        float inv = 1.f / se;
#pragma unroll
        for (int q = 0; q < 4; ++q) {
            float ww = e[q] * inv;
            int i = lane + 32 * q;
            wsm[i] = ww;
            out[(size_t)NG * OUTD + (size_t)g * NODES + i] = ww;
        }
    }
    __syncthreads();

    // ---- v[d] = sum_i w_i * zT[d][i] ----
    if (tid < OUTD) {
        const float* ztf = (const float*)(smc + RING);
        float a = 0.f;
#pragma unroll 4
        for (int i = 0; i < NODES; ++i)
            a = fmaf(wsm[i], ztf[tid * 132 + i], a);
        out[(size_t)g * OUTD + tid] = a;
    }
}

}  // namespace lb

extern "C" void kernel_launch(void* const* d_in, const int* in_sizes, int n_in,
                              void* d_out, int out_size)
{
    (void)in_sizes; (void)n_in; (void)out_size;
    const float* H     = (const float*)d_in[0];
    const float* W_in  = (const float*)d_in[2];
    const float* b_in  = (const float*)d_in[3];
    const float* g_in  = (const float*)d_in[4];
    const float* be_in = (const float*)d_in[5];
    const float* Wb    = (const float*)d_in[6];
    const float* bb    = (const float*)d_in[7];
    const float* gb    = (const float*)d_in[8];
    const float* betab = (const float*)d_in[9];
    const float* W_out = (const float*)d_in[10];
    const float* b_out = (const float*)d_in[11];
    const float* g_out = (const float*)d_in[12];
    const float* be_out= (const float*)d_in[13];
    float* out = (float*)d_out;

    lb::prep<<<960, 256>>>(W_in, Wb, W_out);

    cudaFuncSetAttribute(lb::fused,
                         cudaFuncAttributeMaxDynamicSharedMemorySize,
                         lb::SMEM_BYTES);
    lb::fused<<<lb::NG, lb::TPB, lb::SMEM_BYTES>>>(
        H, b_in, g_in, be_in, bb, gb, betab, b_out, g_out, be_out, out);
}